// round 14
// baseline (speedup 1.0000x reference)
#include <cuda_runtime.h>
#include <cuda_bf16.h>
#include <math.h>
#include <stdint.h>

// ============================================================================
// Fused 8-layer MLP 168->84->42->21->12->10->5->2->1, batch 262144.
// ALL layers on warp-level mma.sync bf16 (3-pass hi/lo split, fp32 accum),
// chained in fragment layout. R14: single-wave hybrid schedule — grid=296
// (148 SM x 2 slots), each warp does 3 dual-tile m32 units + (first 2176
// warps) one single-tile m16 unit. Kills the 3.46-wave ceil(4) tail.
// ============================================================================

#define THREADS 256
#define GRID_CTAS 296
#define TOTAL_WARPS (GRID_CTAS * 8)       // 2368
#define N_DUAL_ITERS 3
#define DUAL_ROWS (N_DUAL_ITERS * TOTAL_WARPS * 32)  // 227328
#define N_SINGLE 2176                     // (262144 - 227328) / 16

// per-layer mma tile counts: NT = n-tiles of 8, KT = k-steps of 16
#define NT1 11
#define KT1 11
#define NT2 6
#define KT2 6
#define NT3 3
#define KT3 3
#define NT4 2
#define KT4 2
#define NT5 2
#define KT5 1
#define NT6 1
#define KT6 1
#define NT7 1
#define KT7 1

// fragment image sizes in uint4 ({hi0,hi1,lo0,lo1} per lane per (j,t))
#define FR1 (NT1 * KT1 * 32)
#define FR2 (NT2 * KT2 * 32)
#define FR3 (NT3 * KT3 * 32)
#define FR4 (NT4 * KT4 * 32)
#define FR5 (NT5 * KT5 * 32)
#define FR6 (NT6 * KT6 * 32)
#define FR7 (NT7 * KT7 * 32)
#define U4_B1 0
#define U4_B2 (U4_B1 + FR1)
#define U4_B3 (U4_B2 + FR2)
#define U4_B4 (U4_B3 + FR3)
#define U4_B5 (U4_B4 + FR4)
#define U4_B6 (U4_B5 + FR5)
#define U4_B7 (U4_B6 + FR6)
#define FR_TOTAL (U4_B7 + FR7)

// aux float layout (biases + final layer)
#define X_B1 0
#define X_B2 84
#define X_B3 126
#define X_B4 147
#define X_B5 159
#define X_B6 169
#define X_B7 174
#define X_W8 176
#define X_B8 178
#define AUX_N 179

// smem layout (bytes)
#define OFF_FR  0
#define OFF_AUX (FR_TOTAL * 16)
#define SMEM_TOTAL (OFF_AUX + ((AUX_N * 4 + 15) & ~15))

// ---------------- device globals ----------------
__device__ __align__(16) uint4 g_fr[FR_TOTAL];
__device__ __align__(16) float g_aux[AUX_N + 1];

// ---------------- helpers ----------------
__device__ __forceinline__ uint32_t pack_bf2(float f0, float f1) {
    uint32_t r;
    asm("cvt.rn.bf16x2.f32 %0, %1, %2;" : "=r"(r) : "f"(f1), "f"(f0));
    return r;
}
__device__ __forceinline__ uint32_t pack_lo_residual(float f0, float f1, uint32_t hi) {
    float r0 = __uint_as_float(hi << 16);
    float r1 = __uint_as_float(hi & 0xFFFF0000u);
    return pack_bf2(f0 - r0, f1 - r1);
}

#define MMA_BF16(c, a0, a1, a2, a3, b0, b1) \
    asm volatile("mma.sync.aligned.m16n8k16.row.col.f32.bf16.bf16.f32 " \
        "{%0,%1,%2,%3}, {%4,%5,%6,%7}, {%8,%9}, {%0,%1,%2,%3};" \
        : "+f"((c)[0]), "+f"((c)[1]), "+f"((c)[2]), "+f"((c)[3]) \
        : "r"(a0), "r"(a1), "r"(a2), "r"(a3), "r"(b0), "r"(b1))

// ---------------- prep kernel ----------------
__device__ void build_frags(const float* __restrict__ W, int out_dim, int in_dim,
                            int NT, int KT, uint4* __restrict__ dst,
                            int tid, int stride)
{
    int total = NT * KT * 32;
    for (int fs = tid; fs < total; fs += stride) {
        int j = fs / (KT * 32);
        int t = (fs / 32) % KT;
        int lane = fs % 32;
        int g = lane >> 2, i = lane & 3;
        int n = 8 * j + g;
        uint32_t hv[2], lv[2];
#pragma unroll
        for (int r = 0; r < 2; ++r) {
            int k0 = 16 * t + 8 * r + 2 * i;
            float w0 = (n < out_dim && k0     < in_dim) ? W[n * in_dim + k0]     : 0.0f;
            float w1 = (n < out_dim && k0 + 1 < in_dim) ? W[n * in_dim + k0 + 1] : 0.0f;
            __nv_bfloat16 h0 = __float2bfloat16(w0), h1 = __float2bfloat16(w1);
            float hf0 = __bfloat162float(h0), hf1 = __bfloat162float(h1);
            __nv_bfloat16 l0 = __float2bfloat16(w0 - hf0), l1 = __float2bfloat16(w1 - hf1);
            hv[r] = ((uint32_t)__bfloat16_as_ushort(h1) << 16) | __bfloat16_as_ushort(h0);
            lv[r] = ((uint32_t)__bfloat16_as_ushort(l1) << 16) | __bfloat16_as_ushort(l0);
        }
        dst[fs] = make_uint4(hv[0], hv[1], lv[0], lv[1]);
    }
}

__global__ void prep_kernel(
    const float* __restrict__ W1, const float* __restrict__ b1,
    const float* __restrict__ W2, const float* __restrict__ b2,
    const float* __restrict__ W3, const float* __restrict__ b3,
    const float* __restrict__ W4, const float* __restrict__ b4,
    const float* __restrict__ W5, const float* __restrict__ b5,
    const float* __restrict__ W6, const float* __restrict__ b6,
    const float* __restrict__ W7, const float* __restrict__ b7,
    const float* __restrict__ W8, const float* __restrict__ b8)
{
    int tid = blockIdx.x * blockDim.x + threadIdx.x;
    int stride = gridDim.x * blockDim.x;

    build_frags(W1, 84, 168, NT1, KT1, g_fr + U4_B1, tid, stride);
    build_frags(W2, 42, 84,  NT2, KT2, g_fr + U4_B2, tid, stride);
    build_frags(W3, 21, 42,  NT3, KT3, g_fr + U4_B3, tid, stride);
    build_frags(W4, 12, 21,  NT4, KT4, g_fr + U4_B4, tid, stride);
    build_frags(W5, 10, 12,  NT5, KT5, g_fr + U4_B5, tid, stride);
    build_frags(W6, 5,  10,  NT6, KT6, g_fr + U4_B6, tid, stride);
    build_frags(W7, 2,  5,   NT7, KT7, g_fr + U4_B7, tid, stride);

    for (int i = tid; i < 84; i += stride) g_aux[X_B1 + i] = b1[i];
    for (int i = tid; i < 42; i += stride) g_aux[X_B2 + i] = b2[i];
    for (int i = tid; i < 21; i += stride) g_aux[X_B3 + i] = b3[i];
    for (int i = tid; i < 12; i += stride) g_aux[X_B4 + i] = b4[i];
    for (int i = tid; i < 10; i += stride) g_aux[X_B5 + i] = b5[i];
    for (int i = tid; i < 5;  i += stride) g_aux[X_B6 + i] = b6[i];
    for (int i = tid; i < 2;  i += stride) g_aux[X_B7 + i] = b7[i];
    for (int i = tid; i < 2;  i += stride) g_aux[X_W8 + i] = W8[i];
    if (tid == 0) g_aux[X_B8] = b8[0];
}

// ---------------- single-tile fragment-chained dense layer ----------------
template<int NT_IN, int KT, int NT_OUT>
__device__ __forceinline__ void frag_layer(
    const float (&accIn)[NT_IN][4], float (&accOut)[NT_OUT][4],
    const uint4* __restrict__ Bf, const float* __restrict__ bias,
    int realN, int lane)
{
    int i = lane & 3;
#pragma unroll
    for (int j = 0; j < NT_OUT; ++j) {
#pragma unroll
        for (int c = 0; c < 4; ++c) accOut[j][c] = 0.f;
    }
#pragma unroll
    for (int s = 0; s < KT; ++s) {
        int jA = 2 * s, jB = 2 * s + 1;
        float f0 = accIn[jA][0], f1 = accIn[jA][1], f2 = accIn[jA][2], f3 = accIn[jA][3];
        float h0 = 0.f, h1 = 0.f, h2 = 0.f, h3 = 0.f;
        if (jB < NT_IN) { h0 = accIn[jB][0]; h1 = accIn[jB][1]; h2 = accIn[jB][2]; h3 = accIn[jB][3]; }
        uint32_t fh0 = pack_bf2(f0, f1), fh1 = pack_bf2(f2, f3);
        uint32_t fh2 = pack_bf2(h0, h1), fh3 = pack_bf2(h2, h3);
        uint32_t fl0 = pack_lo_residual(f0, f1, fh0);
        uint32_t fl1 = pack_lo_residual(f2, f3, fh1);
        uint32_t fl2 = pack_lo_residual(h0, h1, fh2);
        uint32_t fl3 = pack_lo_residual(h2, h3, fh3);
#pragma unroll
        for (int j = 0; j < NT_OUT; ++j) {
            uint4 bf = Bf[(j * KT + s) * 32 + lane];
            MMA_BF16(accOut[j], fh0, fh1, fh2, fh3, bf.x, bf.y);
            MMA_BF16(accOut[j], fl0, fl1, fl2, fl3, bf.x, bf.y);
            MMA_BF16(accOut[j], fh0, fh1, fh2, fh3, bf.z, bf.w);
        }
    }
#pragma unroll
    for (int j = 0; j < NT_OUT; ++j) {
        int col0 = 8 * j + 2 * i, col1 = col0 + 1;
        float bb0 = (col0 < realN) ? bias[col0] : 0.0f;
        float bb1 = (col1 < realN) ? bias[col1] : 0.0f;
        accOut[j][0] = fmaxf(accOut[j][0] + bb0, 0.0f);
        accOut[j][1] = fmaxf(accOut[j][1] + bb1, 0.0f);
        accOut[j][2] = fmaxf(accOut[j][2] + bb0, 0.0f);
        accOut[j][3] = fmaxf(accOut[j][3] + bb1, 0.0f);
    }
}

// ---------------- dual-tile layer (layers 3..7) ----------------
template<int NT_IN, int KT, int NT_OUT>
__device__ __forceinline__ void frag_layer_dual(
    const float (&inA)[NT_IN][4], const float (&inB)[NT_IN][4],
    float (&outA)[NT_OUT][4], float (&outB)[NT_OUT][4],
    const uint4* __restrict__ Bf, const float* __restrict__ bias,
    int realN, int lane)
{
    int i = lane & 3;
#pragma unroll
    for (int j = 0; j < NT_OUT; ++j) {
#pragma unroll
        for (int c = 0; c < 4; ++c) { outA[j][c] = 0.f; outB[j][c] = 0.f; }
    }
#pragma unroll
    for (int s = 0; s < KT; ++s) {
        int jA = 2 * s, jB = 2 * s + 1;
        float fA0 = inA[jA][0], fA1 = inA[jA][1], fA2 = inA[jA][2], fA3 = inA[jA][3];
        float hA0 = 0.f, hA1 = 0.f, hA2 = 0.f, hA3 = 0.f;
        if (jB < NT_IN) { hA0 = inA[jB][0]; hA1 = inA[jB][1]; hA2 = inA[jB][2]; hA3 = inA[jB][3]; }
        uint32_t ah0 = pack_bf2(fA0, fA1), ah1 = pack_bf2(fA2, fA3);
        uint32_t ah2 = pack_bf2(hA0, hA1), ah3 = pack_bf2(hA2, hA3);
        uint32_t al0 = pack_lo_residual(fA0, fA1, ah0);
        uint32_t al1 = pack_lo_residual(fA2, fA3, ah1);
        uint32_t al2 = pack_lo_residual(hA0, hA1, ah2);
        uint32_t al3 = pack_lo_residual(hA2, hA3, ah3);
        float fB0 = inB[jA][0], fB1 = inB[jA][1], fB2 = inB[jA][2], fB3 = inB[jA][3];
        float hB0 = 0.f, hB1 = 0.f, hB2 = 0.f, hB3 = 0.f;
        if (jB < NT_IN) { hB0 = inB[jB][0]; hB1 = inB[jB][1]; hB2 = inB[jB][2]; hB3 = inB[jB][3]; }
        uint32_t bh0 = pack_bf2(fB0, fB1), bh1 = pack_bf2(fB2, fB3);
        uint32_t bh2 = pack_bf2(hB0, hB1), bh3 = pack_bf2(hB2, hB3);
        uint32_t bl0 = pack_lo_residual(fB0, fB1, bh0);
        uint32_t bl1 = pack_lo_residual(fB2, fB3, bh1);
        uint32_t bl2 = pack_lo_residual(hB0, hB1, bh2);
        uint32_t bl3 = pack_lo_residual(hB2, hB3, bh3);
#pragma unroll
        for (int j = 0; j < NT_OUT; ++j) {
            uint4 bf = Bf[(j * KT + s) * 32 + lane];
            MMA_BF16(outA[j], ah0, ah1, ah2, ah3, bf.x, bf.y);
            MMA_BF16(outB[j], bh0, bh1, bh2, bh3, bf.x, bf.y);
            MMA_BF16(outA[j], al0, al1, al2, al3, bf.x, bf.y);
            MMA_BF16(outB[j], bl0, bl1, bl2, bl3, bf.x, bf.y);
            MMA_BF16(outA[j], ah0, ah1, ah2, ah3, bf.z, bf.w);
            MMA_BF16(outB[j], bh0, bh1, bh2, bh3, bf.z, bf.w);
        }
    }
#pragma unroll
    for (int j = 0; j < NT_OUT; ++j) {
        int col0 = 8 * j + 2 * i, col1 = col0 + 1;
        float bb0 = (col0 < realN) ? bias[col0] : 0.0f;
        float bb1 = (col1 < realN) ? bias[col1] : 0.0f;
        outA[j][0] = fmaxf(outA[j][0] + bb0, 0.0f);
        outA[j][1] = fmaxf(outA[j][1] + bb1, 0.0f);
        outA[j][2] = fmaxf(outA[j][2] + bb0, 0.0f);
        outA[j][3] = fmaxf(outA[j][3] + bb1, 0.0f);
        outB[j][0] = fmaxf(outB[j][0] + bb0, 0.0f);
        outB[j][1] = fmaxf(outB[j][1] + bb1, 0.0f);
        outB[j][2] = fmaxf(outB[j][2] + bb0, 0.0f);
        outB[j][3] = fmaxf(outB[j][3] + bb1, 0.0f);
    }
}

// ---------------- dual-tile m32 unit (verbatim R12 body) ----------------
__device__ __forceinline__ void mlp_unit_dual(
    const float* __restrict__ x, float* __restrict__ out, int rowBase,
    const uint4* __restrict__ sFr, const float* __restrict__ sAux, int lane)
{
    int g = lane >> 2, i = lane & 3;
    const uint4* B1f = sFr + U4_B1;
    const float* xr0 = x + (size_t)(rowBase + g) * 168;
    const float* xr1 = xr0 + 8 * 168;
    const float* xr2 = xr0 + 16 * 168;
    const float* xr3 = xr0 + 24 * 168;

    float accA[NT1][4], accB[NT1][4];
#pragma unroll
    for (int j = 0; j < NT1; ++j) {
#pragma unroll
        for (int c = 0; c < 4; ++c) { accA[j][c] = 0.f; accB[j][c] = 0.f; }
    }

    for (int t = 0; t < KT1; ++t) {
        int c0 = 16 * t + 2 * i;
        int c1 = c0 + 8;
        float2 vA0 = *(const float2*)(xr0 + c0);
        float2 vA1 = *(const float2*)(xr1 + c0);
        float2 vB0 = *(const float2*)(xr2 + c0);
        float2 vB1 = *(const float2*)(xr3 + c0);
        float2 vA2, vA3, vB2, vB3;
        if (c1 < 167) {
            vA2 = *(const float2*)(xr0 + c1);
            vA3 = *(const float2*)(xr1 + c1);
            vB2 = *(const float2*)(xr2 + c1);
            vB3 = *(const float2*)(xr3 + c1);
        } else {
            vA2 = make_float2(0.f, 0.f); vA3 = make_float2(0.f, 0.f);
            vB2 = make_float2(0.f, 0.f); vB3 = make_float2(0.f, 0.f);
        }
        uint32_t A0h = pack_bf2(vA0.x, vA0.y), A1h = pack_bf2(vA1.x, vA1.y);
        uint32_t A2h = pack_bf2(vA2.x, vA2.y), A3h = pack_bf2(vA3.x, vA3.y);
        uint32_t A0l = pack_lo_residual(vA0.x, vA0.y, A0h);
        uint32_t A1l = pack_lo_residual(vA1.x, vA1.y, A1h);
        uint32_t A2l = pack_lo_residual(vA2.x, vA2.y, A2h);
        uint32_t A3l = pack_lo_residual(vA3.x, vA3.y, A3h);
        uint32_t B0h = pack_bf2(vB0.x, vB0.y), B1h_ = pack_bf2(vB1.x, vB1.y);
        uint32_t B2h = pack_bf2(vB2.x, vB2.y), B3h = pack_bf2(vB3.x, vB3.y);
        uint32_t B0l = pack_lo_residual(vB0.x, vB0.y, B0h);
        uint32_t B1l_ = pack_lo_residual(vB1.x, vB1.y, B1h_);
        uint32_t B2l = pack_lo_residual(vB2.x, vB2.y, B2h);
        uint32_t B3l = pack_lo_residual(vB3.x, vB3.y, B3h);

#pragma unroll
        for (int j = 0; j < NT1; ++j) {
            uint4 bf = B1f[(j * KT1 + t) * 32 + lane];
            MMA_BF16(accA[j], A0h, A1h, A2h, A3h, bf.x, bf.y);
            MMA_BF16(accB[j], B0h, B1h_, B2h, B3h, bf.x, bf.y);
            MMA_BF16(accA[j], A0l, A1l, A2l, A3l, bf.x, bf.y);
            MMA_BF16(accB[j], B0l, B1l_, B2l, B3l, bf.x, bf.y);
            MMA_BF16(accA[j], A0h, A1h, A2h, A3h, bf.z, bf.w);
            MMA_BF16(accB[j], B0h, B1h_, B2h, B3h, bf.z, bf.w);
        }
    }

#pragma unroll
    for (int j = 0; j < NT1; ++j) {
        int col0 = 8 * j + 2 * i, col1 = col0 + 1;
        float bb0 = (col0 < 84) ? sAux[X_B1 + col0] : 0.0f;
        float bb1 = (col1 < 84) ? sAux[X_B1 + col1] : 0.0f;
        accA[j][0] = fmaxf(accA[j][0] + bb0, 0.0f);
        accA[j][1] = fmaxf(accA[j][1] + bb1, 0.0f);
        accA[j][2] = fmaxf(accA[j][2] + bb0, 0.0f);
        accA[j][3] = fmaxf(accA[j][3] + bb1, 0.0f);
        accB[j][0] = fmaxf(accB[j][0] + bb0, 0.0f);
        accB[j][1] = fmaxf(accB[j][1] + bb1, 0.0f);
        accB[j][2] = fmaxf(accB[j][2] + bb0, 0.0f);
        accB[j][3] = fmaxf(accB[j][3] + bb1, 0.0f);
    }

    float acc2A[NT2][4];
    frag_layer<NT1, KT2, NT2>(accA, acc2A, sFr + U4_B2, sAux + X_B2, 42, lane);
    float acc2B[NT2][4];
    frag_layer<NT1, KT2, NT2>(accB, acc2B, sFr + U4_B2, sAux + X_B2, 42, lane);

    float acc3A[NT3][4], acc3B[NT3][4];
    frag_layer_dual<NT2, KT3, NT3>(acc2A, acc2B, acc3A, acc3B, sFr + U4_B3, sAux + X_B3, 21, lane);
    float acc4A[NT4][4], acc4B[NT4][4];
    frag_layer_dual<NT3, KT4, NT4>(acc3A, acc3B, acc4A, acc4B, sFr + U4_B4, sAux + X_B4, 12, lane);
    float acc5A[NT5][4], acc5B[NT5][4];
    frag_layer_dual<NT4, KT5, NT5>(acc4A, acc4B, acc5A, acc5B, sFr + U4_B5, sAux + X_B5, 10, lane);
    float acc6A[NT6][4], acc6B[NT6][4];
    frag_layer_dual<NT5, KT6, NT6>(acc5A, acc5B, acc6A, acc6B, sFr + U4_B6, sAux + X_B6, 5, lane);
    float acc7A[NT7][4], acc7B[NT7][4];
    frag_layer_dual<NT6, KT7, NT7>(acc6A, acc6B, acc7A, acc7B, sFr + U4_B7, sAux + X_B7, 2, lane);

    if (i == 0) {
        float w0 = sAux[X_W8], w1 = sAux[X_W8 + 1], bb = sAux[X_B8];
        float zA0 = fmaf(acc7A[0][1], w1, fmaf(acc7A[0][0], w0, bb));
        float zA1 = fmaf(acc7A[0][3], w1, fmaf(acc7A[0][2], w0, bb));
        float zB0 = fmaf(acc7B[0][1], w1, fmaf(acc7B[0][0], w0, bb));
        float zB1 = fmaf(acc7B[0][3], w1, fmaf(acc7B[0][2], w0, bb));
        out[rowBase + g]      = 1.0f / (1.0f + expf(-zA0));
        out[rowBase + 8 + g]  = 1.0f / (1.0f + expf(-zA1));
        out[rowBase + 16 + g] = 1.0f / (1.0f + expf(-zB0));
        out[rowBase + 24 + g] = 1.0f / (1.0f + expf(-zB1));
    }
}

// ---------------- single-tile m16 unit (tail coverage) ----------------
__device__ __forceinline__ void mlp_unit_single(
    const float* __restrict__ x, float* __restrict__ out, int rowBase,
    const uint4* __restrict__ sFr, const float* __restrict__ sAux, int lane)
{
    int g = lane >> 2, i = lane & 3;
    const uint4* B1f = sFr + U4_B1;
    const float* xr0 = x + (size_t)(rowBase + g) * 168;
    const float* xr1 = xr0 + 8 * 168;

    float acc[NT1][4];
#pragma unroll
    for (int j = 0; j < NT1; ++j) {
#pragma unroll
        for (int c = 0; c < 4; ++c) acc[j][c] = 0.f;
    }

    for (int t = 0; t < KT1; ++t) {
        int c0 = 16 * t + 2 * i;
        int c1 = c0 + 8;
        float2 v0 = *(const float2*)(xr0 + c0);
        float2 v1 = *(const float2*)(xr1 + c0);
        float2 v2, v3;
        if (c1 < 167) {
            v2 = *(const float2*)(xr0 + c1);
            v3 = *(const float2*)(xr1 + c1);
        } else {
            v2 = make_float2(0.f, 0.f); v3 = make_float2(0.f, 0.f);
        }
        uint32_t a0h = pack_bf2(v0.x, v0.y), a1h = pack_bf2(v1.x, v1.y);
        uint32_t a2h = pack_bf2(v2.x, v2.y), a3h = pack_bf2(v3.x, v3.y);
        uint32_t a0l = pack_lo_residual(v0.x, v0.y, a0h);
        uint32_t a1l = pack_lo_residual(v1.x, v1.y, a1h);
        uint32_t a2l = pack_lo_residual(v2.x, v2.y, a2h);
        uint32_t a3l = pack_lo_residual(v3.x, v3.y, a3h);
#pragma unroll
        for (int j = 0; j < NT1; ++j) {
            uint4 bf = B1f[(j * KT1 + t) * 32 + lane];
            MMA_BF16(acc[j], a0h, a1h, a2h, a3h, bf.x, bf.y);
            MMA_BF16(acc[j], a0l, a1l, a2l, a3l, bf.x, bf.y);
            MMA_BF16(acc[j], a0h, a1h, a2h, a3h, bf.z, bf.w);
        }
    }

#pragma unroll
    for (int j = 0; j < NT1; ++j) {
        int col0 = 8 * j + 2 * i, col1 = col0 + 1;
        float bb0 = (col0 < 84) ? sAux[X_B1 + col0] : 0.0f;
        float bb1 = (col1 < 84) ? sAux[X_B1 + col1] : 0.0f;
        acc[j][0] = fmaxf(acc[j][0] + bb0, 0.0f);
        acc[j][1] = fmaxf(acc[j][1] + bb1, 0.0f);
        acc[j][2] = fmaxf(acc[j][2] + bb0, 0.0f);
        acc[j][3] = fmaxf(acc[j][3] + bb1, 0.0f);
    }

    float acc2[NT2][4];
    frag_layer<NT1, KT2, NT2>(acc, acc2, sFr + U4_B2, sAux + X_B2, 42, lane);
    float acc3[NT3][4];
    frag_layer<NT2, KT3, NT3>(acc2, acc3, sFr + U4_B3, sAux + X_B3, 21, lane);
    float acc4[NT4][4];
    frag_layer<NT3, KT4, NT4>(acc3, acc4, sFr + U4_B4, sAux + X_B4, 12, lane);
    float acc5[NT5][4];
    frag_layer<NT4, KT5, NT5>(acc4, acc5, sFr + U4_B5, sAux + X_B5, 10, lane);
    float acc6[NT6][4];
    frag_layer<NT5, KT6, NT6>(acc5, acc6, sFr + U4_B6, sAux + X_B6, 5, lane);
    float acc7[NT7][4];
    frag_layer<NT6, KT7, NT7>(acc6, acc7, sFr + U4_B7, sAux + X_B7, 2, lane);

    if (i == 0) {
        float w0 = sAux[X_W8], w1 = sAux[X_W8 + 1], bb = sAux[X_B8];
        float z0 = fmaf(acc7[0][1], w1, fmaf(acc7[0][0], w0, bb));
        float z1 = fmaf(acc7[0][3], w1, fmaf(acc7[0][2], w0, bb));
        out[rowBase + g]     = 1.0f / (1.0f + expf(-z0));
        out[rowBase + 8 + g] = 1.0f / (1.0f + expf(-z1));
    }
}

// ---------------- main kernel: grid = 296, single wave ----------------
__global__ void __launch_bounds__(THREADS, 2) mlp_mma_kernel(
    const float* __restrict__ x, float* __restrict__ out)
{
    extern __shared__ __align__(16) unsigned char smem[];
    int tid = threadIdx.x;
    int warp = tid >> 5;
    int lane = tid & 31;

    // fill smem: fragment images + aux
    {
        const uint4* src = (const uint4*)g_fr;
        uint4* dst = (uint4*)(smem + OFF_FR);
        for (int q = tid; q < FR_TOTAL; q += THREADS) dst[q] = src[q];
        float* sa = (float*)(smem + OFF_AUX);
        for (int q = tid; q < AUX_N; q += THREADS) sa[q] = g_aux[q];
    }
    __syncthreads();

    const uint4* sFr = (const uint4*)(smem + OFF_FR);
    const float* sAux = (const float*)(smem + OFF_AUX);

    int gwarp = blockIdx.x * 8 + warp;

    // 3 dual-tile m32 units per warp (outer loop kept rolled -> one code copy)
#pragma unroll 1
    for (int it = 0; it < N_DUAL_ITERS; ++it) {
        int rowBase = (gwarp + it * TOTAL_WARPS) * 32;
        mlp_unit_dual(x, out, rowBase, sFr, sAux, lane);
    }

    // single-tile m16 tail: first 2176 warps cover the remaining 34816 rows
    if (gwarp < N_SINGLE) {
        int rowBase = DUAL_ROWS + gwarp * 16;
        mlp_unit_single(x, out, rowBase, sFr, sAux, lane);
    }
}

// ---------------- launch ----------------
extern "C" void kernel_launch(void* const* d_in, const int* in_sizes, int n_in,
                              void* d_out, int out_size) {
    const float* x  = (const float*)d_in[0];
    const float* W1 = (const float*)d_in[1];
    const float* b1 = (const float*)d_in[2];
    const float* W2 = (const float*)d_in[3];
    const float* b2 = (const float*)d_in[4];
    const float* W3 = (const float*)d_in[5];
    const float* b3 = (const float*)d_in[6];
    const float* W4 = (const float*)d_in[7];
    const float* b4 = (const float*)d_in[8];
    const float* W5 = (const float*)d_in[9];
    const float* b5 = (const float*)d_in[10];
    const float* W6 = (const float*)d_in[11];
    const float* b6 = (const float*)d_in[12];
    const float* W7 = (const float*)d_in[13];
    const float* b7 = (const float*)d_in[14];
    const float* W8 = (const float*)d_in[15];
    const float* b8 = (const float*)d_in[16];
    float* out = (float*)d_out;

    prep_kernel<<<64, 256>>>(W1, b1, W2, b2, W3, b3, W4, b4,
                             W5, b5, W6, b6, W7, b7, W8, b8);

    cudaFuncSetAttribute(mlp_mma_kernel, cudaFuncAttributeMaxDynamicSharedMemorySize, SMEM_TOTAL);
    mlp_mma_kernel<<<GRID_CTAS, THREADS, SMEM_TOTAL>>>(x, out);
}

// round 15
// speedup vs baseline: 1.1135x; 1.1135x over previous
#include <cuda_runtime.h>
#include <cuda_bf16.h>
#include <math.h>
#include <stdint.h>

// ============================================================================
// Fused 8-layer MLP 168->84->42->21->12->10->5->2->1, batch 262144.
// ALL layers on warp-level mma.sync bf16 (3-pass hi/lo split, fp32 accum),
// chained in fragment layout. R15: R12 base + j-paired MMA issue (dependent
// accumulator reuse distance 2->4 in layer 1, 1->2 in frag_layer).
// ============================================================================

#define THREADS 256
#define ROWS_PER_CTA 256

// per-layer mma tile counts: NT = n-tiles of 8, KT = k-steps of 16
#define NT1 11
#define KT1 11
#define NT2 6
#define KT2 6
#define NT3 3
#define KT3 3
#define NT4 2
#define KT4 2
#define NT5 2
#define KT5 1
#define NT6 1
#define KT6 1
#define NT7 1
#define KT7 1

// fragment image sizes in uint4 ({hi0,hi1,lo0,lo1} per lane per (j,t))
#define FR1 (NT1 * KT1 * 32)
#define FR2 (NT2 * KT2 * 32)
#define FR3 (NT3 * KT3 * 32)
#define FR4 (NT4 * KT4 * 32)
#define FR5 (NT5 * KT5 * 32)
#define FR6 (NT6 * KT6 * 32)
#define FR7 (NT7 * KT7 * 32)
#define U4_B1 0
#define U4_B2 (U4_B1 + FR1)
#define U4_B3 (U4_B2 + FR2)
#define U4_B4 (U4_B3 + FR3)
#define U4_B5 (U4_B4 + FR4)
#define U4_B6 (U4_B5 + FR5)
#define U4_B7 (U4_B6 + FR6)
#define FR_TOTAL (U4_B7 + FR7)

// aux float layout (biases + final layer)
#define X_B1 0
#define X_B2 84
#define X_B3 126
#define X_B4 147
#define X_B5 159
#define X_B6 169
#define X_B7 174
#define X_W8 176
#define X_B8 178
#define AUX_N 179

// smem layout (bytes)
#define OFF_FR  0
#define OFF_AUX (FR_TOTAL * 16)
#define SMEM_TOTAL (OFF_AUX + ((AUX_N * 4 + 15) & ~15))

// ---------------- device globals ----------------
__device__ __align__(16) uint4 g_fr[FR_TOTAL];
__device__ __align__(16) float g_aux[AUX_N + 1];

// ---------------- helpers ----------------
__device__ __forceinline__ uint32_t pack_bf2(float f0, float f1) {
    uint32_t r;
    asm("cvt.rn.bf16x2.f32 %0, %1, %2;" : "=r"(r) : "f"(f1), "f"(f0));
    return r;
}
__device__ __forceinline__ uint32_t pack_lo_residual(float f0, float f1, uint32_t hi) {
    float r0 = __uint_as_float(hi << 16);
    float r1 = __uint_as_float(hi & 0xFFFF0000u);
    return pack_bf2(f0 - r0, f1 - r1);
}

#define MMA_BF16(c, a0, a1, a2, a3, b0, b1) \
    asm volatile("mma.sync.aligned.m16n8k16.row.col.f32.bf16.bf16.f32 " \
        "{%0,%1,%2,%3}, {%4,%5,%6,%7}, {%8,%9}, {%0,%1,%2,%3};" \
        : "+f"((c)[0]), "+f"((c)[1]), "+f"((c)[2]), "+f"((c)[3]) \
        : "r"(a0), "r"(a1), "r"(a2), "r"(a3), "r"(b0), "r"(b1))

// ---------------- prep kernel ----------------
__device__ void build_frags(const float* __restrict__ W, int out_dim, int in_dim,
                            int NT, int KT, uint4* __restrict__ dst,
                            int tid, int stride)
{
    int total = NT * KT * 32;
    for (int fs = tid; fs < total; fs += stride) {
        int j = fs / (KT * 32);
        int t = (fs / 32) % KT;
        int lane = fs % 32;
        int g = lane >> 2, i = lane & 3;
        int n = 8 * j + g;
        uint32_t hv[2], lv[2];
#pragma unroll
        for (int r = 0; r < 2; ++r) {
            int k0 = 16 * t + 8 * r + 2 * i;
            float w0 = (n < out_dim && k0     < in_dim) ? W[n * in_dim + k0]     : 0.0f;
            float w1 = (n < out_dim && k0 + 1 < in_dim) ? W[n * in_dim + k0 + 1] : 0.0f;
            __nv_bfloat16 h0 = __float2bfloat16(w0), h1 = __float2bfloat16(w1);
            float hf0 = __bfloat162float(h0), hf1 = __bfloat162float(h1);
            __nv_bfloat16 l0 = __float2bfloat16(w0 - hf0), l1 = __float2bfloat16(w1 - hf1);
            hv[r] = ((uint32_t)__bfloat16_as_ushort(h1) << 16) | __bfloat16_as_ushort(h0);
            lv[r] = ((uint32_t)__bfloat16_as_ushort(l1) << 16) | __bfloat16_as_ushort(l0);
        }
        dst[fs] = make_uint4(hv[0], hv[1], lv[0], lv[1]);
    }
}

__global__ void prep_kernel(
    const float* __restrict__ W1, const float* __restrict__ b1,
    const float* __restrict__ W2, const float* __restrict__ b2,
    const float* __restrict__ W3, const float* __restrict__ b3,
    const float* __restrict__ W4, const float* __restrict__ b4,
    const float* __restrict__ W5, const float* __restrict__ b5,
    const float* __restrict__ W6, const float* __restrict__ b6,
    const float* __restrict__ W7, const float* __restrict__ b7,
    const float* __restrict__ W8, const float* __restrict__ b8)
{
    int tid = blockIdx.x * blockDim.x + threadIdx.x;
    int stride = gridDim.x * blockDim.x;

    build_frags(W1, 84, 168, NT1, KT1, g_fr + U4_B1, tid, stride);
    build_frags(W2, 42, 84,  NT2, KT2, g_fr + U4_B2, tid, stride);
    build_frags(W3, 21, 42,  NT3, KT3, g_fr + U4_B3, tid, stride);
    build_frags(W4, 12, 21,  NT4, KT4, g_fr + U4_B4, tid, stride);
    build_frags(W5, 10, 12,  NT5, KT5, g_fr + U4_B5, tid, stride);
    build_frags(W6, 5,  10,  NT6, KT6, g_fr + U4_B6, tid, stride);
    build_frags(W7, 2,  5,   NT7, KT7, g_fr + U4_B7, tid, stride);

    for (int i = tid; i < 84; i += stride) g_aux[X_B1 + i] = b1[i];
    for (int i = tid; i < 42; i += stride) g_aux[X_B2 + i] = b2[i];
    for (int i = tid; i < 21; i += stride) g_aux[X_B3 + i] = b3[i];
    for (int i = tid; i < 12; i += stride) g_aux[X_B4 + i] = b4[i];
    for (int i = tid; i < 10; i += stride) g_aux[X_B5 + i] = b5[i];
    for (int i = tid; i < 5;  i += stride) g_aux[X_B6 + i] = b6[i];
    for (int i = tid; i < 2;  i += stride) g_aux[X_B7 + i] = b7[i];
    for (int i = tid; i < 2;  i += stride) g_aux[X_W8 + i] = W8[i];
    if (tid == 0) g_aux[X_B8] = b8[0];
}

// ---------------- single-tile fragment-chained dense layer ----------------
// R15: j processed in pairs -> dependent accumulator reuse distance 2.
template<int NT_IN, int KT, int NT_OUT>
__device__ __forceinline__ void frag_layer(
    const float (&accIn)[NT_IN][4], float (&accOut)[NT_OUT][4],
    const uint4* __restrict__ Bf, const float* __restrict__ bias,
    int realN, int lane)
{
    int i = lane & 3;
#pragma unroll
    for (int j = 0; j < NT_OUT; ++j) {
#pragma unroll
        for (int c = 0; c < 4; ++c) accOut[j][c] = 0.f;
    }
#pragma unroll
    for (int s = 0; s < KT; ++s) {
        int jA = 2 * s, jB = 2 * s + 1;
        float f0 = accIn[jA][0], f1 = accIn[jA][1], f2 = accIn[jA][2], f3 = accIn[jA][3];
        float h0 = 0.f, h1 = 0.f, h2 = 0.f, h3 = 0.f;
        if (jB < NT_IN) { h0 = accIn[jB][0]; h1 = accIn[jB][1]; h2 = accIn[jB][2]; h3 = accIn[jB][3]; }
        uint32_t fh0 = pack_bf2(f0, f1), fh1 = pack_bf2(f2, f3);
        uint32_t fh2 = pack_bf2(h0, h1), fh3 = pack_bf2(h2, h3);
        uint32_t fl0 = pack_lo_residual(f0, f1, fh0);
        uint32_t fl1 = pack_lo_residual(f2, f3, fh1);
        uint32_t fl2 = pack_lo_residual(h0, h1, fh2);
        uint32_t fl3 = pack_lo_residual(h2, h3, fh3);
        // paired j: distance-2 dependent chains
#pragma unroll
        for (int jp = 0; jp + 1 < NT_OUT; jp += 2) {
            uint4 b0 = Bf[((jp)     * KT + s) * 32 + lane];
            uint4 b1v = Bf[((jp + 1) * KT + s) * 32 + lane];
            MMA_BF16(accOut[jp],     fh0, fh1, fh2, fh3, b0.x, b0.y);
            MMA_BF16(accOut[jp + 1], fh0, fh1, fh2, fh3, b1v.x, b1v.y);
            MMA_BF16(accOut[jp],     fl0, fl1, fl2, fl3, b0.x, b0.y);
            MMA_BF16(accOut[jp + 1], fl0, fl1, fl2, fl3, b1v.x, b1v.y);
            MMA_BF16(accOut[jp],     fh0, fh1, fh2, fh3, b0.z, b0.w);
            MMA_BF16(accOut[jp + 1], fh0, fh1, fh2, fh3, b1v.z, b1v.w);
        }
        if (NT_OUT & 1) {
            int j = NT_OUT - 1;
            uint4 bf = Bf[(j * KT + s) * 32 + lane];
            MMA_BF16(accOut[j], fh0, fh1, fh2, fh3, bf.x, bf.y);
            MMA_BF16(accOut[j], fl0, fl1, fl2, fl3, bf.x, bf.y);
            MMA_BF16(accOut[j], fh0, fh1, fh2, fh3, bf.z, bf.w);
        }
    }
#pragma unroll
    for (int j = 0; j < NT_OUT; ++j) {
        int col0 = 8 * j + 2 * i, col1 = col0 + 1;
        float bb0 = (col0 < realN) ? bias[col0] : 0.0f;
        float bb1 = (col1 < realN) ? bias[col1] : 0.0f;
        accOut[j][0] = fmaxf(accOut[j][0] + bb0, 0.0f);
        accOut[j][1] = fmaxf(accOut[j][1] + bb1, 0.0f);
        accOut[j][2] = fmaxf(accOut[j][2] + bb0, 0.0f);
        accOut[j][3] = fmaxf(accOut[j][3] + bb1, 0.0f);
    }
}

// ---------------- dual-tile layer (layers 3..7) ----------------
template<int NT_IN, int KT, int NT_OUT>
__device__ __forceinline__ void frag_layer_dual(
    const float (&inA)[NT_IN][4], const float (&inB)[NT_IN][4],
    float (&outA)[NT_OUT][4], float (&outB)[NT_OUT][4],
    const uint4* __restrict__ Bf, const float* __restrict__ bias,
    int realN, int lane)
{
    int i = lane & 3;
#pragma unroll
    for (int j = 0; j < NT_OUT; ++j) {
#pragma unroll
        for (int c = 0; c < 4; ++c) { outA[j][c] = 0.f; outB[j][c] = 0.f; }
    }
#pragma unroll
    for (int s = 0; s < KT; ++s) {
        int jA = 2 * s, jB = 2 * s + 1;
        float fA0 = inA[jA][0], fA1 = inA[jA][1], fA2 = inA[jA][2], fA3 = inA[jA][3];
        float hA0 = 0.f, hA1 = 0.f, hA2 = 0.f, hA3 = 0.f;
        if (jB < NT_IN) { hA0 = inA[jB][0]; hA1 = inA[jB][1]; hA2 = inA[jB][2]; hA3 = inA[jB][3]; }
        uint32_t ah0 = pack_bf2(fA0, fA1), ah1 = pack_bf2(fA2, fA3);
        uint32_t ah2 = pack_bf2(hA0, hA1), ah3 = pack_bf2(hA2, hA3);
        uint32_t al0 = pack_lo_residual(fA0, fA1, ah0);
        uint32_t al1 = pack_lo_residual(fA2, fA3, ah1);
        uint32_t al2 = pack_lo_residual(hA0, hA1, ah2);
        uint32_t al3 = pack_lo_residual(hA2, hA3, ah3);
        float fB0 = inB[jA][0], fB1 = inB[jA][1], fB2 = inB[jA][2], fB3 = inB[jA][3];
        float hB0 = 0.f, hB1 = 0.f, hB2 = 0.f, hB3 = 0.f;
        if (jB < NT_IN) { hB0 = inB[jB][0]; hB1 = inB[jB][1]; hB2 = inB[jB][2]; hB3 = inB[jB][3]; }
        uint32_t bh0 = pack_bf2(fB0, fB1), bh1 = pack_bf2(fB2, fB3);
        uint32_t bh2 = pack_bf2(hB0, hB1), bh3 = pack_bf2(hB2, hB3);
        uint32_t bl0 = pack_lo_residual(fB0, fB1, bh0);
        uint32_t bl1 = pack_lo_residual(fB2, fB3, bh1);
        uint32_t bl2 = pack_lo_residual(hB0, hB1, bh2);
        uint32_t bl3 = pack_lo_residual(hB2, hB3, bh3);
#pragma unroll
        for (int j = 0; j < NT_OUT; ++j) {
            uint4 bf = Bf[(j * KT + s) * 32 + lane];
            MMA_BF16(outA[j], ah0, ah1, ah2, ah3, bf.x, bf.y);
            MMA_BF16(outB[j], bh0, bh1, bh2, bh3, bf.x, bf.y);
            MMA_BF16(outA[j], al0, al1, al2, al3, bf.x, bf.y);
            MMA_BF16(outB[j], bl0, bl1, bl2, bl3, bf.x, bf.y);
            MMA_BF16(outA[j], ah0, ah1, ah2, ah3, bf.z, bf.w);
            MMA_BF16(outB[j], bh0, bh1, bh2, bh3, bf.z, bf.w);
        }
    }
#pragma unroll
    for (int j = 0; j < NT_OUT; ++j) {
        int col0 = 8 * j + 2 * i, col1 = col0 + 1;
        float bb0 = (col0 < realN) ? bias[col0] : 0.0f;
        float bb1 = (col1 < realN) ? bias[col1] : 0.0f;
        outA[j][0] = fmaxf(outA[j][0] + bb0, 0.0f);
        outA[j][1] = fmaxf(outA[j][1] + bb1, 0.0f);
        outA[j][2] = fmaxf(outA[j][2] + bb0, 0.0f);
        outA[j][3] = fmaxf(outA[j][3] + bb1, 0.0f);
        outB[j][0] = fmaxf(outB[j][0] + bb0, 0.0f);
        outB[j][1] = fmaxf(outB[j][1] + bb1, 0.0f);
        outB[j][2] = fmaxf(outB[j][2] + bb0, 0.0f);
        outB[j][3] = fmaxf(outB[j][3] + bb1, 0.0f);
    }
}

// ---------------- main kernel ----------------
// grid = batch/256; CTA = 8 warps, each warp two m16 tiles (32 rows).
__global__ void __launch_bounds__(THREADS, 2) mlp_mma_kernel(
    const float* __restrict__ x, float* __restrict__ out)
{
    extern __shared__ __align__(16) unsigned char smem[];
    int tid = threadIdx.x;
    int warp = tid >> 5;
    int lane = tid & 31;
    int g = lane >> 2, i = lane & 3;

    // fill smem: fragment images + aux
    {
        const uint4* src = (const uint4*)g_fr;
        uint4* dst = (uint4*)(smem + OFF_FR);
        for (int q = tid; q < FR_TOTAL; q += THREADS) dst[q] = src[q];
        float* sa = (float*)(smem + OFF_AUX);
        for (int q = tid; q < AUX_N; q += THREADS) sa[q] = g_aux[q];
    }
    __syncthreads();

    const uint4* sFr = (const uint4*)(smem + OFF_FR);
    const uint4* B1f = sFr + U4_B1;
    const float* sAux = (const float*)(smem + OFF_AUX);

    int rowBase = blockIdx.x * ROWS_PER_CTA + warp * 32;
    const float* xr0 = x + (size_t)(rowBase + g) * 168;  // tile A rows g, g+8
    const float* xr1 = xr0 + 8 * 168;
    const float* xr2 = xr0 + 16 * 168;                   // tile B rows 16+g, 24+g
    const float* xr3 = xr0 + 24 * 168;

    // ================= layer 1: two m16 tiles share B loads =================
    float accA[NT1][4], accB[NT1][4];
#pragma unroll
    for (int j = 0; j < NT1; ++j) {
#pragma unroll
        for (int c = 0; c < 4; ++c) { accA[j][c] = 0.f; accB[j][c] = 0.f; }
    }

    for (int t = 0; t < KT1; ++t) {
        int c0 = 16 * t + 2 * i;
        int c1 = c0 + 8;
        float2 vA0 = *(const float2*)(xr0 + c0);
        float2 vA1 = *(const float2*)(xr1 + c0);
        float2 vB0 = *(const float2*)(xr2 + c0);
        float2 vB1 = *(const float2*)(xr3 + c0);
        float2 vA2, vA3, vB2, vB3;
        if (c1 < 167) {   // t==10 -> c1 >= 168: zero-pad
            vA2 = *(const float2*)(xr0 + c1);
            vA3 = *(const float2*)(xr1 + c1);
            vB2 = *(const float2*)(xr2 + c1);
            vB3 = *(const float2*)(xr3 + c1);
        } else {
            vA2 = make_float2(0.f, 0.f); vA3 = make_float2(0.f, 0.f);
            vB2 = make_float2(0.f, 0.f); vB3 = make_float2(0.f, 0.f);
        }
        uint32_t A0h = pack_bf2(vA0.x, vA0.y), A1h = pack_bf2(vA1.x, vA1.y);
        uint32_t A2h = pack_bf2(vA2.x, vA2.y), A3h = pack_bf2(vA3.x, vA3.y);
        uint32_t A0l = pack_lo_residual(vA0.x, vA0.y, A0h);
        uint32_t A1l = pack_lo_residual(vA1.x, vA1.y, A1h);
        uint32_t A2l = pack_lo_residual(vA2.x, vA2.y, A2h);
        uint32_t A3l = pack_lo_residual(vA3.x, vA3.y, A3h);
        uint32_t B0h = pack_bf2(vB0.x, vB0.y), B1h_ = pack_bf2(vB1.x, vB1.y);
        uint32_t B2h = pack_bf2(vB2.x, vB2.y), B3h = pack_bf2(vB3.x, vB3.y);
        uint32_t B0l = pack_lo_residual(vB0.x, vB0.y, B0h);
        uint32_t B1l_ = pack_lo_residual(vB1.x, vB1.y, B1h_);
        uint32_t B2l = pack_lo_residual(vB2.x, vB2.y, B2h);
        uint32_t B3l = pack_lo_residual(vB3.x, vB3.y, B3h);

        // paired j: A/B x {j0,j1} -> dependent reuse distance 4
#pragma unroll
        for (int jp = 0; jp + 1 < NT1; jp += 2) {
            uint4 b0 = B1f[((jp)     * KT1 + t) * 32 + lane];
            uint4 b1v = B1f[((jp + 1) * KT1 + t) * 32 + lane];
            MMA_BF16(accA[jp],     A0h, A1h, A2h, A3h, b0.x, b0.y);
            MMA_BF16(accB[jp],     B0h, B1h_, B2h, B3h, b0.x, b0.y);
            MMA_BF16(accA[jp + 1], A0h, A1h, A2h, A3h, b1v.x, b1v.y);
            MMA_BF16(accB[jp + 1], B0h, B1h_, B2h, B3h, b1v.x, b1v.y);
            MMA_BF16(accA[jp],     A0l, A1l, A2l, A3l, b0.x, b0.y);
            MMA_BF16(accB[jp],     B0l, B1l_, B2l, B3l, b0.x, b0.y);
            MMA_BF16(accA[jp + 1], A0l, A1l, A2l, A3l, b1v.x, b1v.y);
            MMA_BF16(accB[jp + 1], B0l, B1l_, B2l, B3l, b1v.x, b1v.y);
            MMA_BF16(accA[jp],     A0h, A1h, A2h, A3h, b0.z, b0.w);
            MMA_BF16(accB[jp],     B0h, B1h_, B2h, B3h, b0.z, b0.w);
            MMA_BF16(accA[jp + 1], A0h, A1h, A2h, A3h, b1v.z, b1v.w);
            MMA_BF16(accB[jp + 1], B0h, B1h_, B2h, B3h, b1v.z, b1v.w);
        }
        {   // leftover j = 10
            const int j = NT1 - 1;
            uint4 bf = B1f[(j * KT1 + t) * 32 + lane];
            MMA_BF16(accA[j], A0h, A1h, A2h, A3h, bf.x, bf.y);
            MMA_BF16(accB[j], B0h, B1h_, B2h, B3h, bf.x, bf.y);
            MMA_BF16(accA[j], A0l, A1l, A2l, A3l, bf.x, bf.y);
            MMA_BF16(accB[j], B0l, B1l_, B2l, B3l, bf.x, bf.y);
            MMA_BF16(accA[j], A0h, A1h, A2h, A3h, bf.z, bf.w);
            MMA_BF16(accB[j], B0h, B1h_, B2h, B3h, bf.z, bf.w);
        }
    }

    // ============ epilogue 1: bias + relu (both tiles, in regs) ============
#pragma unroll
    for (int j = 0; j < NT1; ++j) {
        int col0 = 8 * j + 2 * i, col1 = col0 + 1;
        float bb0 = (col0 < 84) ? sAux[X_B1 + col0] : 0.0f;
        float bb1 = (col1 < 84) ? sAux[X_B1 + col1] : 0.0f;
        accA[j][0] = fmaxf(accA[j][0] + bb0, 0.0f);
        accA[j][1] = fmaxf(accA[j][1] + bb1, 0.0f);
        accA[j][2] = fmaxf(accA[j][2] + bb0, 0.0f);
        accA[j][3] = fmaxf(accA[j][3] + bb1, 0.0f);
        accB[j][0] = fmaxf(accB[j][0] + bb0, 0.0f);
        accB[j][1] = fmaxf(accB[j][1] + bb1, 0.0f);
        accB[j][2] = fmaxf(accB[j][2] + bb0, 0.0f);
        accB[j][3] = fmaxf(accB[j][3] + bb1, 0.0f);
    }

    // ======= layer 2: per tile (register ceiling), tile A then tile B =======
    float acc2A[NT2][4];
    frag_layer<NT1, KT2, NT2>(accA, acc2A, sFr + U4_B2, sAux + X_B2, 42, lane);
    float acc2B[NT2][4];
    frag_layer<NT1, KT2, NT2>(accB, acc2B, sFr + U4_B2, sAux + X_B2, 42, lane);

    // ======= layers 3..7: dual-tile, shared frag loads, 2x ILP =======
    float acc3A[NT3][4], acc3B[NT3][4];
    frag_layer_dual<NT2, KT3, NT3>(acc2A, acc2B, acc3A, acc3B, sFr + U4_B3, sAux + X_B3, 21, lane);
    float acc4A[NT4][4], acc4B[NT4][4];
    frag_layer_dual<NT3, KT4, NT4>(acc3A, acc3B, acc4A, acc4B, sFr + U4_B4, sAux + X_B4, 12, lane);
    float acc5A[NT5][4], acc5B[NT5][4];
    frag_layer_dual<NT4, KT5, NT5>(acc4A, acc4B, acc5A, acc5B, sFr + U4_B5, sAux + X_B5, 10, lane);
    float acc6A[NT6][4], acc6B[NT6][4];
    frag_layer_dual<NT5, KT6, NT6>(acc5A, acc5B, acc6A, acc6B, sFr + U4_B6, sAux + X_B6, 5, lane);
    float acc7A[NT7][4], acc7B[NT7][4];
    frag_layer_dual<NT6, KT7, NT7>(acc6A, acc6B, acc7A, acc7B, sFr + U4_B7, sAux + X_B7, 2, lane);

    // ======= layer 8 + sigmoid, both tiles; lanes i==0 hold cols 0,1 =======
    if (i == 0) {
        float w0 = sAux[X_W8], w1 = sAux[X_W8 + 1], bb = sAux[X_B8];
        float zA0 = fmaf(acc7A[0][1], w1, fmaf(acc7A[0][0], w0, bb));   // row g
        float zA1 = fmaf(acc7A[0][3], w1, fmaf(acc7A[0][2], w0, bb));   // row g+8
        float zB0 = fmaf(acc7B[0][1], w1, fmaf(acc7B[0][0], w0, bb));   // row 16+g
        float zB1 = fmaf(acc7B[0][3], w1, fmaf(acc7B[0][2], w0, bb));   // row 24+g
        out[rowBase + g]      = 1.0f / (1.0f + expf(-zA0));
        out[rowBase + 8 + g]  = 1.0f / (1.0f + expf(-zA1));
        out[rowBase + 16 + g] = 1.0f / (1.0f + expf(-zB0));
        out[rowBase + 24 + g] = 1.0f / (1.0f + expf(-zB1));
    }
}

// ---------------- launch ----------------
extern "C" void kernel_launch(void* const* d_in, const int* in_sizes, int n_in,
                              void* d_out, int out_size) {
    const float* x  = (const float*)d_in[0];
    const float* W1 = (const float*)d_in[1];
    const float* b1 = (const float*)d_in[2];
    const float* W2 = (const float*)d_in[3];
    const float* b2 = (const float*)d_in[4];
    const float* W3 = (const float*)d_in[5];
    const float* b3 = (const float*)d_in[6];
    const float* W4 = (const float*)d_in[7];
    const float* b4 = (const float*)d_in[8];
    const float* W5 = (const float*)d_in[9];
    const float* b5 = (const float*)d_in[10];
    const float* W6 = (const float*)d_in[11];
    const float* b6 = (const float*)d_in[12];
    const float* W7 = (const float*)d_in[13];
    const float* b7 = (const float*)d_in[14];
    const float* W8 = (const float*)d_in[15];
    const float* b8 = (const float*)d_in[16];
    float* out = (float*)d_out;

    int batch = in_sizes[0] / 168;
    int grid = batch / ROWS_PER_CTA;

    prep_kernel<<<64, 256>>>(W1, b1, W2, b2, W3, b3, W4, b4,
                             W5, b5, W6, b6, W7, b7, W8, b8);

    cudaFuncSetAttribute(mlp_mma_kernel, cudaFuncAttributeMaxDynamicSharedMemorySize, SMEM_TOTAL);
    mlp_mma_kernel<<<grid, THREADS, SMEM_TOTAL>>>(x, out);
}